// round 8
// baseline (speedup 1.0000x reference)
#include <cuda_runtime.h>
#include <math.h>

#define BQ   4
#define CCH  3
#define HH   512
#define WW   512
#define NPL  32
#define TW   32            // tile width  (8 threads x 4 px)
#define TH   16            // tile height
#define HALO 15
#define SW   (TW + 2*HALO) // 62 valid halo columns
#define SWP  64            // padded shared row stride (floats)
#define SH   (TH + 2*HALO) // 46 halo rows

#define SYMI(d) ((d) < 16 ? (d) : 30 - (d))

// Global weight table (folded symmetric halves) + bucket midpoints.
__device__ float g_wtab[NPL][16];
__device__ float g_msh[32];

// ---------------------------------------------------------------------------
// Parallel table build: 512 threads, one (plane, tap) each; width-16 shfl
// reduction for the normalization sum (2*sum(head)+center == full-kernel sum).
// ---------------------------------------------------------------------------
__global__ void build_table_kernel() {
    const int t = threadIdx.x;          // 0..511
    const int i = t >> 4;               // plane
    const int j = t & 15;               // folded tap 0..15 (15 = center)
    const double step = 50.0 / 31.0;
    const float cocf = (float)(i * step);
    float e;
    if (cocf < 0.5f) {
        e = (j == 15) ? 1.0f : 0.0f;    // identity plane
    } else {
        double cd = (double)cocf;
        int k = (int)(2.0 * cd + 1.0);
        if (!(k & 1)) k++;
        if (k > 31) k = 31;
        const int half = k >> 1;
        const int c = j - 15;           // <= 0
        if (-c > half) {
            e = 0.0f;
        } else {
            double sg = cd / 2.355;
            float inv2 = (float)(1.0 / (2.0 * sg * sg));
            e = expf(-(float)(c * c) * inv2);
        }
    }
    float contrib = (j < 15) ? 2.0f * e : e;    // full-kernel sum via fold
#pragma unroll
    for (int off = 8; off; off >>= 1)
        contrib += __shfl_xor_sync(0xffffffffu, contrib, off, 16);
    g_wtab[i][j] = e / contrib;
    if (t < 31)
        g_msh[t] = ((float)(t * step) + (float)((t + 1) * step)) * 0.5f;
}

// ---------------------------------------------------------------------------
// Main kernel: 32x16 tile, 4 px/thread, folded rows, streaming fold window.
// ---------------------------------------------------------------------------
__global__ void __launch_bounds__(128, 5)
defocus_kernel(const float* __restrict__ sharp,
               const float* __restrict__ coc,
               float* __restrict__ out) {
    __shared__ float tile[CCH][SH][SWP];   // 35328 B (tile only)

    const int tx  = threadIdx.x;           // 0..7
    const int ty  = threadIdx.y;           // 0..15
    const int tid = ty * 8 + tx;
    const int x0 = blockIdx.x * TW;
    const int y0 = blockIdx.y * TH;
    const int b  = blockIdx.z;

    // ---- tile + halo load (zero outside image) ----
    const float* sb = sharp + (size_t)b * CCH * HH * WW;
#pragma unroll
    for (int c = 0; c < CCH; c++) {
        const float* sc = sb + (size_t)c * HH * WW;
#pragma unroll
        for (int u = 0; u < (SH * SWP) / 128; u++) {   // 23 iters, exact
            int idx = u * 128 + tid;
            int r  = idx / SWP;
            int cc = idx - r * SWP;
            int gx = x0 - HALO + cc;
            int gy = y0 - HALO + r;
            float v = 0.0f;
            if (cc < SW && (unsigned)gx < (unsigned)WW && (unsigned)gy < (unsigned)HH)
                v = sc[gy * WW + gx];
            tile[c][r][cc] = v;
        }
    }
    __syncthreads();

    const int xA = x0 + 4 * tx;
    const int y  = y0 + ty;

    // ---- plane bucketing (exact reference midpoints, from global) ----
    const float4 c4 = *(const float4*)(coc + ((size_t)b * HH + y) * WW + xA);
    int p0 = 0, p1 = 0, p2 = 0, p3 = 0;
#pragma unroll
    for (int i = 0; i < 31; i++) {
        float m = g_msh[i];
        p0 += c4.x > m; p1 += c4.y > m; p2 += c4.z > m; p3 += c4.w > m;
    }

    // ---- symmetric half-kernels into registers ----
    float wA[16], wB[16], wC[16], wD[16];
#pragma unroll
    for (int j = 0; j < 16; j++) {
        wA[j] = g_wtab[p0][j]; wB[j] = g_wtab[p1][j];
        wC[j] = g_wtab[p2][j]; wD[j] = g_wtab[p3][j];
    }

    float* ob = out + (size_t)b * CCH * HH * WW;

    // ---- channel-outer loop: only 4 live accumulators ----
#pragma unroll 1
    for (int c = 0; c < CCH; c++) {
        const float* tc = &tile[c][0][0];
        float accA = 0.f, accB = 0.f, accC = 0.f, accD = 0.f;

#pragma unroll 2
        for (int s = 0; s < 16; s++) {
            const float hs = (s == 15) ? 0.5f : 1.0f;   // self-pair at center
            const float gA = g_wtab[p0][s] * hs;
            const float gB = g_wtab[p1][s] * hs;
            const float gC = g_wtab[p2][s] * hs;
            const float gD = g_wtab[p3][s] * hs;

            const float* ra = tc + (ty + s) * SWP + 4 * tx;
            const float* rb = tc + (ty + 30 - s) * SWP + 4 * tx;

            float Fp[4], Fc[4];
            {
                float4 qa = *(const float4*)ra;
                float4 qb = *(const float4*)rb;
                Fp[0] = qa.x + qb.x; Fp[1] = qa.y + qb.y;
                Fp[2] = qa.z + qb.z; Fp[3] = qa.w + qb.w;
            }
            float a = 0.f, bb = 0.f, cc2 = 0.f, d = 0.f;
#pragma unroll
            for (int m = 1; m <= 8; m++) {
                float4 qa = *(const float4*)(ra + 4 * m);
                float4 qb = *(const float4*)(rb + 4 * m);
                Fc[0] = qa.x + qb.x; Fc[1] = qa.y + qb.y;
                Fc[2] = qa.z + qb.z; Fc[3] = qa.w + qb.w;
#pragma unroll
                for (int t = 0; t < 4; t++) {
                    const int dx = 4 * (m - 1) + t;
                    if (dx <= 30) {
                        const int sj = SYMI(dx);
                        a   += wA[sj] * Fp[t];
                        bb  += wB[sj] * ((t < 3) ? Fp[t + 1] : Fc[0]);
                        cc2 += wC[sj] * ((t < 2) ? Fp[t + 2] : Fc[t - 2]);
                        d   += wD[sj] * ((t < 1) ? Fp[t + 3] : Fc[t - 1]);
                    }
                }
                Fp[0] = Fc[0]; Fp[1] = Fc[1]; Fp[2] = Fc[2]; Fp[3] = Fc[3];
            }
            accA += gA * a;
            accB += gB * bb;
            accC += gC * cc2;
            accD += gD * d;
        }
        *(float4*)(ob + ((size_t)c * HH + y) * WW + xA) =
            make_float4(accA, accB, accC, accD);
    }
}

// ---------------------------------------------------------------------------
extern "C" void kernel_launch(void* const* d_in, const int* in_sizes, int n_in,
                              void* d_out, int out_size) {
    const float* sharp = (const float*)d_in[0];
    const float* coc   = (const float*)d_in[1];
    if (n_in >= 2 && in_sizes[0] == BQ * HH * WW && in_sizes[1] == BQ * CCH * HH * WW) {
        sharp = (const float*)d_in[1];   // defensive input-order swap
        coc   = (const float*)d_in[0];
    }
    float* out = (float*)d_out;

    build_table_kernel<<<1, 512>>>();
    dim3 grid(WW / TW, HH / TH, BQ);    // (16, 32, 4)
    dim3 block(8, 16);
    defocus_kernel<<<grid, block>>>(sharp, coc, out);
}

// round 9
// speedup vs baseline: 1.3951x; 1.3951x over previous
#include <cuda_runtime.h>
#include <math.h>

#define BQ   4
#define CCH  3
#define HH   512
#define WW   512
#define NPL  32
#define TW   32            // tile width  (8 threads x 4 px)
#define TH   16            // tile height
#define HALO 15
#define SW   (TW + 2*HALO) // 62 valid halo columns
#define SWP  64            // padded shared row stride (floats)
#define SH   (TH + 2*HALO) // 46 halo rows

#define SYMI(d) ((d) < 16 ? (d) : 30 - (d))

// Reference-exact bucket midpoints as compile-time constants
// (double linspace -> f32 -> f32 midpoint, same recipe as the numpy ref).
__device__ constexpr float midp(int i) {
    return ((float)(i * (50.0 / 31.0)) + (float)((i + 1) * (50.0 / 31.0))) * 0.5f;
}

__global__ void __launch_bounds__(128, 5)
defocus_kernel(const float* __restrict__ sharp,
               const float* __restrict__ coc,
               float* __restrict__ out) {
    __shared__ float tile[CCH][SH][SWP];   // 35328 B
    __shared__ float wt[16][32];           // 2048 B, transposed folded table:
                                           // wt[tap][plane] -> bank = plane

    const int tx  = threadIdx.x;           // 0..7
    const int ty  = threadIdx.y;           // 0..15
    const int tid = ty * 8 + tx;
    const int x0 = blockIdx.x * TW;
    const int y0 = blockIdx.y * TH;
    const int b  = blockIdx.z;

    // ---- weight table phase 1: unnormalized entries (4 expf/thread) ----
    const double step = 50.0 / 31.0;
#pragma unroll
    for (int idx = tid; idx < NPL * 16; idx += 128) {
        const int i = idx & 31;            // plane
        const int j = idx >> 5;            // folded tap 0..15 (15 = center)
        const float cocf = (float)(i * step);
        float e;
        if (cocf < 0.5f) {
            e = (j == 15) ? 1.0f : 0.0f;   // identity plane
        } else {
            double cd = (double)cocf;
            int k = (int)(2.0 * cd + 1.0);
            if (!(k & 1)) k++;
            if (k > 31) k = 31;
            const int half = k >> 1;
            const int d = 15 - j;          // distance from center, >= 0
            if (d > half) {
                e = 0.0f;
            } else {
                double sg = cd / 2.355;
                float inv2 = (float)(1.0 / (2.0 * sg * sg));
                e = expf(-(float)(d * d) * inv2);
            }
        }
        wt[j][i] = e;
    }

    // ---- tile + halo load (zero outside image) ----
    const float* sb = sharp + (size_t)b * CCH * HH * WW;
#pragma unroll
    for (int c = 0; c < CCH; c++) {
        const float* sc = sb + (size_t)c * HH * WW;
#pragma unroll
        for (int u = 0; u < (SH * SWP) / 128; u++) {   // 23 iters, exact
            int idx = u * 128 + tid;
            int r  = idx / SWP;
            int cc = idx - r * SWP;
            int gx = x0 - HALO + cc;
            int gy = y0 - HALO + r;
            float v = 0.0f;
            if (cc < SW && (unsigned)gx < (unsigned)WW && (unsigned)gy < (unsigned)HH)
                v = sc[gy * WW + gx];
            tile[c][r][cc] = v;
        }
    }
    __syncthreads();

    // ---- weight table phase 2: normalize each plane (column read, bank=tid) ----
    if (tid < NPL) {
        float s = wt[15][tid];
#pragma unroll
        for (int j = 0; j < 15; j++) s += 2.0f * wt[j][tid];
        const float inv = 1.0f / s;
#pragma unroll
        for (int j = 0; j < 16; j++) wt[j][tid] *= inv;
    }
    __syncthreads();

    const int xA = x0 + 4 * tx;
    const int y  = y0 + ty;

    // ---- plane bucketing (immediate-constant midpoints) ----
    const float4 c4 = *(const float4*)(coc + ((size_t)b * HH + y) * WW + xA);
    int p0 = 0, p1 = 0, p2 = 0, p3 = 0;
#pragma unroll
    for (int i = 0; i < 31; i++) {
        const float m = midp(i);
        p0 += c4.x > m; p1 += c4.y > m; p2 += c4.z > m; p3 += c4.w > m;
    }

    // ---- symmetric half-kernels into registers (conflict-free LDS) ----
    float wA[16], wB[16], wC[16], wD[16];
#pragma unroll
    for (int j = 0; j < 16; j++) {
        wA[j] = wt[j][p0]; wB[j] = wt[j][p1];
        wC[j] = wt[j][p2]; wD[j] = wt[j][p3];
    }

    float* ob = out + (size_t)b * CCH * HH * WW;

    // ---- channel-outer loop: only 4 live accumulators ----
#pragma unroll 1
    for (int c = 0; c < CCH; c++) {
        const float* tc = &tile[c][0][0];
        float accA = 0.f, accB = 0.f, accC = 0.f, accD = 0.f;

#pragma unroll 2
        for (int s = 0; s < 16; s++) {
            const float hs = (s == 15) ? 0.5f : 1.0f;   // self-pair at center
            const float gA = wt[s][p0] * hs;
            const float gB = wt[s][p1] * hs;
            const float gC = wt[s][p2] * hs;
            const float gD = wt[s][p3] * hs;

            const float* ra = tc + (ty + s) * SWP + 4 * tx;
            const float* rb = tc + (ty + 30 - s) * SWP + 4 * tx;

            float Fp[4], Fc[4];
            {
                float4 qa = *(const float4*)ra;
                float4 qb = *(const float4*)rb;
                Fp[0] = qa.x + qb.x; Fp[1] = qa.y + qb.y;
                Fp[2] = qa.z + qb.z; Fp[3] = qa.w + qb.w;
            }
            float a = 0.f, bb = 0.f, cc2 = 0.f, d = 0.f;
#pragma unroll
            for (int m = 1; m <= 8; m++) {
                float4 qa = *(const float4*)(ra + 4 * m);
                float4 qb = *(const float4*)(rb + 4 * m);
                Fc[0] = qa.x + qb.x; Fc[1] = qa.y + qb.y;
                Fc[2] = qa.z + qb.z; Fc[3] = qa.w + qb.w;
#pragma unroll
                for (int t = 0; t < 4; t++) {
                    const int dx = 4 * (m - 1) + t;
                    if (dx <= 30) {
                        const int sj = SYMI(dx);
                        a   += wA[sj] * Fp[t];
                        bb  += wB[sj] * ((t < 3) ? Fp[t + 1] : Fc[0]);
                        cc2 += wC[sj] * ((t < 2) ? Fp[t + 2] : Fc[t - 2]);
                        d   += wD[sj] * ((t < 1) ? Fp[t + 3] : Fc[t - 1]);
                    }
                }
                Fp[0] = Fc[0]; Fp[1] = Fc[1]; Fp[2] = Fc[2]; Fp[3] = Fc[3];
            }
            accA += gA * a;
            accB += gB * bb;
            accC += gC * cc2;
            accD += gD * d;
        }
        *(float4*)(ob + ((size_t)c * HH + y) * WW + xA) =
            make_float4(accA, accB, accC, accD);
    }
}

// ---------------------------------------------------------------------------
extern "C" void kernel_launch(void* const* d_in, const int* in_sizes, int n_in,
                              void* d_out, int out_size) {
    const float* sharp = (const float*)d_in[0];
    const float* coc   = (const float*)d_in[1];
    if (n_in >= 2 && in_sizes[0] == BQ * HH * WW && in_sizes[1] == BQ * CCH * HH * WW) {
        sharp = (const float*)d_in[1];   // defensive input-order swap
        coc   = (const float*)d_in[0];
    }
    float* out = (float*)d_out;

    dim3 grid(WW / TW, HH / TH, BQ);    // (16, 32, 4)
    dim3 block(8, 16);
    defocus_kernel<<<grid, block>>>(sharp, coc, out);
}

// round 10
// speedup vs baseline: 1.4303x; 1.0252x over previous
#include <cuda_runtime.h>
#include <math.h>
#include <stdint.h>

#define BQ   4
#define CCH  3
#define HH   512
#define WW   512
#define NPL  32
#define TW   32            // tile width  (8 threads x 4 px)
#define TH   16            // tile height
#define HALO 15
#define SW   (TW + 2*HALO) // 62 valid halo columns
#define SWP  64            // padded shared row stride (floats)
#define SH   (TH + 2*HALO) // 46 halo rows

#define SYMI(d) ((d) < 16 ? (d) : 30 - (d))

// Reference-exact bucket midpoints as compile-time constants.
__device__ constexpr float midp(int i) {
    return ((float)(i * (50.0 / 31.0)) + (float)((i + 1) * (50.0 / 31.0))) * 0.5f;
}

__device__ __forceinline__ void cp_async4(uint32_t daddr, const void* src, int srcsize) {
    asm volatile("cp.async.ca.shared.global [%0], [%1], 4, %2;"
                 :: "r"(daddr), "l"(src), "r"(srcsize) : "memory");
}
__device__ __forceinline__ void cp_commit() {
    asm volatile("cp.async.commit_group;" ::: "memory");
}
template <int N>
__device__ __forceinline__ void cp_wait() {
    asm volatile("cp.async.wait_group %0;" :: "n"(N) : "memory");
}

__global__ void __launch_bounds__(128, 5)
defocus_kernel(const float* __restrict__ sharp,
               const float* __restrict__ coc,
               float* __restrict__ out) {
    __shared__ float tile[CCH][SH][SWP];   // 35328 B
    __shared__ float wt[16][32];           // transposed folded table (bank=plane)

    const int tx  = threadIdx.x;           // 0..7
    const int ty  = threadIdx.y;           // 0..15
    const int tid = ty * 8 + tx;
    const int x0 = blockIdx.x * TW;
    const int y0 = blockIdx.y * TH;
    const int b  = blockIdx.z;

    // ---- 1. async tile loads: one commit group per channel ----
    const float* sb = sharp + (size_t)b * CCH * HH * WW;
#pragma unroll
    for (int c = 0; c < CCH; c++) {
        const float* sc = sb + (size_t)c * HH * WW;
#pragma unroll
        for (int u = 0; u < (SH * SWP) / 128; u++) {   // 23 iters, exact
            int idx = u * 128 + tid;
            int r  = idx >> 6;                         // /SWP
            int cc = idx & 63;
            int gx = x0 - HALO + cc;
            int gy = y0 - HALO + r;
            bool ok = (cc < SW) && ((unsigned)gx < (unsigned)WW)
                                && ((unsigned)gy < (unsigned)HH);
            const float* src = sc + (ok ? (gy * WW + gx) : 0);
            uint32_t daddr = (uint32_t)__cvta_generic_to_shared(&tile[c][r][cc]);
            cp_async4(daddr, src, ok ? 4 : 0);         // zfill outside image
        }
        cp_commit();
    }

    // ---- 2. weight table phase 1 (overlaps DRAM flight) ----
    const double step = 50.0 / 31.0;
#pragma unroll
    for (int idx = tid; idx < NPL * 16; idx += 128) {
        const int i = idx & 31;            // plane
        const int j = idx >> 5;            // folded tap 0..15 (15 = center)
        const float cocf = (float)(i * step);
        float e;
        if (cocf < 0.5f) {
            e = (j == 15) ? 1.0f : 0.0f;
        } else {
            double cd = (double)cocf;
            int k = (int)(2.0 * cd + 1.0);
            if (!(k & 1)) k++;
            if (k > 31) k = 31;
            const int half = k >> 1;
            const int d = 15 - j;
            if (d > half) {
                e = 0.0f;
            } else {
                double sg = cd / 2.355;
                float inv2 = (float)(1.0 / (2.0 * sg * sg));
                e = expf(-(float)(d * d) * inv2);
            }
        }
        wt[j][i] = e;
    }

    // ---- early coc load + bucketing (fills flight latency) ----
    const int xA = x0 + 4 * tx;
    const int y  = y0 + ty;
    const float4 c4 = *(const float4*)(coc + ((size_t)b * HH + y) * WW + xA);
    int p0 = 0, p1 = 0, p2 = 0, p3 = 0;
#pragma unroll
    for (int i = 0; i < 31; i++) {
        const float m = midp(i);
        p0 += c4.x > m; p1 += c4.y > m; p2 += c4.z > m; p3 += c4.w > m;
    }

    // ---- 3. channel 0 landed + phase-1 weights visible ----
    cp_wait<2>();
    __syncthreads();

    // ---- 4. normalize each plane column (bank = tid, conflict-free) ----
    if (tid < NPL) {
        float s = wt[15][tid];
#pragma unroll
        for (int j = 0; j < 15; j++) s += 2.0f * wt[j][tid];
        const float inv = 1.0f / s;
#pragma unroll
        for (int j = 0; j < 16; j++) wt[j][tid] *= inv;
    }
    __syncthreads();

    // ---- symmetric half-kernels into registers (conflict-free LDS) ----
    float wA[16], wB[16], wC[16], wD[16];
#pragma unroll
    for (int j = 0; j < 16; j++) {
        wA[j] = wt[j][p0]; wB[j] = wt[j][p1];
        wC[j] = wt[j][p2]; wD[j] = wt[j][p3];
    }

    float* ob = out + (size_t)b * CCH * HH * WW;

    // ---- channel-outer loop; channels 1,2 land under channel-0 compute ----
#pragma unroll 1
    for (int c = 0; c < CCH; c++) {
        if (c == 1) { cp_wait<1>(); __syncthreads(); }
        if (c == 2) { cp_wait<0>(); __syncthreads(); }

        const float* tc = &tile[c][0][0];
        float accA = 0.f, accB = 0.f, accC = 0.f, accD = 0.f;

#pragma unroll 2
        for (int s = 0; s < 16; s++) {
            const float hs = (s == 15) ? 0.5f : 1.0f;   // self-pair at center
            const float gA = wt[s][p0] * hs;
            const float gB = wt[s][p1] * hs;
            const float gC = wt[s][p2] * hs;
            const float gD = wt[s][p3] * hs;

            const float* ra = tc + (ty + s) * SWP + 4 * tx;
            const float* rb = tc + (ty + 30 - s) * SWP + 4 * tx;

            float Fp[4], Fc[4];
            {
                float4 qa = *(const float4*)ra;
                float4 qb = *(const float4*)rb;
                Fp[0] = qa.x + qb.x; Fp[1] = qa.y + qb.y;
                Fp[2] = qa.z + qb.z; Fp[3] = qa.w + qb.w;
            }
            float a = 0.f, bb = 0.f, cc2 = 0.f, d = 0.f;
#pragma unroll
            for (int m = 1; m <= 8; m++) {
                float4 qa = *(const float4*)(ra + 4 * m);
                float4 qb = *(const float4*)(rb + 4 * m);
                Fc[0] = qa.x + qb.x; Fc[1] = qa.y + qb.y;
                Fc[2] = qa.z + qb.z; Fc[3] = qa.w + qb.w;
#pragma unroll
                for (int t = 0; t < 4; t++) {
                    const int dx = 4 * (m - 1) + t;
                    if (dx <= 30) {
                        const int sj = SYMI(dx);
                        a   += wA[sj] * Fp[t];
                        bb  += wB[sj] * ((t < 3) ? Fp[t + 1] : Fc[0]);
                        cc2 += wC[sj] * ((t < 2) ? Fp[t + 2] : Fc[t - 2]);
                        d   += wD[sj] * ((t < 1) ? Fp[t + 3] : Fc[t - 1]);
                    }
                }
                Fp[0] = Fc[0]; Fp[1] = Fc[1]; Fp[2] = Fc[2]; Fp[3] = Fc[3];
            }
            accA += gA * a;
            accB += gB * bb;
            accC += gC * cc2;
            accD += gD * d;
        }
        *(float4*)(ob + ((size_t)c * HH + y) * WW + xA) =
            make_float4(accA, accB, accC, accD);
    }
}

// ---------------------------------------------------------------------------
extern "C" void kernel_launch(void* const* d_in, const int* in_sizes, int n_in,
                              void* d_out, int out_size) {
    const float* sharp = (const float*)d_in[0];
    const float* coc   = (const float*)d_in[1];
    if (n_in >= 2 && in_sizes[0] == BQ * HH * WW && in_sizes[1] == BQ * CCH * HH * WW) {
        sharp = (const float*)d_in[1];   // defensive input-order swap
        coc   = (const float*)d_in[0];
    }
    float* out = (float*)d_out;

    dim3 grid(WW / TW, HH / TH, BQ);    // (16, 32, 4)
    dim3 block(8, 16);
    defocus_kernel<<<grid, block>>>(sharp, coc, out);
}

// round 11
// speedup vs baseline: 1.4306x; 1.0002x over previous
#include <cuda_runtime.h>
#include <math.h>
#include <stdint.h>

#define BQ   4
#define CCH  3
#define HH   512
#define WW   512
#define NPL  32
#define TW   32            // tile width  (8 threads x 4 px)
#define TH   16            // tile height
#define HALO_L 16          // left halo (16B-aligned quads)
#define HALO_R 15
#define SWP  64            // = SW: 16 quads per row, zero waste
#define SH   (TH + 30 + 1) // 46 halo rows (15 up, 15 down)
#define QPR  16            // quads per row
#define NQ   (SH * QPR)    // 736 quads per channel

#define SYMI(d) ((d) < 16 ? (d) : 30 - (d))

// Reference-exact bucket midpoints as compile-time constants.
__device__ constexpr float midp(int i) {
    return ((float)(i * (50.0 / 31.0)) + (float)((i + 1) * (50.0 / 31.0))) * 0.5f;
}

__device__ __forceinline__ void cp_async16(uint32_t daddr, const void* src, int srcsize) {
    asm volatile("cp.async.cg.shared.global [%0], [%1], 16, %2;"
                 :: "r"(daddr), "l"(src), "r"(srcsize) : "memory");
}
__device__ __forceinline__ void cp_commit() {
    asm volatile("cp.async.commit_group;" ::: "memory");
}
template <int N>
__device__ __forceinline__ void cp_wait() {
    asm volatile("cp.async.wait_group %0;" :: "n"(N) : "memory");
}

__global__ void __launch_bounds__(128, 5)
defocus_kernel(const float* __restrict__ sharp,
               const float* __restrict__ coc,
               float* __restrict__ out) {
    __shared__ float tile[CCH][SH][SWP];   // 35328 B
    __shared__ float wt[16][32];           // transposed folded table (bank=plane)

    const int tx  = threadIdx.x;           // 0..7
    const int ty  = threadIdx.y;           // 0..15
    const int tid = ty * 8 + tx;
    const int x0 = blockIdx.x * TW;
    const int y0 = blockIdx.y * TH;
    const int b  = blockIdx.z;

    // ---- 1. async tile loads: 16B quads, zfill borders, group per channel ----
    // tile col cc <-> gx = x0 - 16 + cc ; row r <-> gy = y0 - 15 + r.
    // W=512 is quad-divisible -> every quad fully in or fully out.
    const float* sb = sharp + (size_t)b * CCH * HH * WW;
#pragma unroll
    for (int c = 0; c < CCH; c++) {
        const float* sc = sb + (size_t)c * HH * WW;
#pragma unroll
        for (int u = 0; u < 6; u++) {                  // ceil(736/128)
            int qidx = u * 128 + tid;
            if (qidx < NQ) {
                int r  = qidx >> 4;                    // /QPR
                int q  = qidx & 15;
                int gx = x0 - HALO_L + 4 * q;          // 16B-aligned
                int gy = y0 - 15 + r;
                bool ok = ((unsigned)gx <= (unsigned)(WW - 4)) &&
                          ((unsigned)gy <  (unsigned)HH);
                const float* src = sc + (ok ? (gy * WW + gx) : 0);
                uint32_t daddr = (uint32_t)__cvta_generic_to_shared(&tile[c][r][4 * q]);
                cp_async16(daddr, src, ok ? 16 : 0);   // zfill outside image
            }
        }
        cp_commit();
    }

    // ---- 2. weight table phase 1 (overlaps DRAM flight) ----
    const double step = 50.0 / 31.0;
#pragma unroll
    for (int idx = tid; idx < NPL * 16; idx += 128) {
        const int i = idx & 31;            // plane
        const int j = idx >> 5;            // folded tap 0..15 (15 = center)
        const float cocf = (float)(i * step);
        float e;
        if (cocf < 0.5f) {
            e = (j == 15) ? 1.0f : 0.0f;
        } else {
            double cd = (double)cocf;
            int k = (int)(2.0 * cd + 1.0);
            if (!(k & 1)) k++;
            if (k > 31) k = 31;
            const int half = k >> 1;
            const int d = 15 - j;
            if (d > half) {
                e = 0.0f;
            } else {
                double sg = cd / 2.355;
                float inv2 = (float)(1.0 / (2.0 * sg * sg));
                e = expf(-(float)(d * d) * inv2);
            }
        }
        wt[j][i] = e;
    }

    // ---- early coc load + bucketing (fills flight latency) ----
    const int xA = x0 + 4 * tx;
    const int y  = y0 + ty;
    const float4 c4 = *(const float4*)(coc + ((size_t)b * HH + y) * WW + xA);
    int p0 = 0, p1 = 0, p2 = 0, p3 = 0;
#pragma unroll
    for (int i = 0; i < 31; i++) {
        const float m = midp(i);
        p0 += c4.x > m; p1 += c4.y > m; p2 += c4.z > m; p3 += c4.w > m;
    }

    // ---- 3. channel 0 landed + phase-1 weights visible ----
    cp_wait<2>();
    __syncthreads();

    // ---- 4. normalize each plane column (bank = tid, conflict-free) ----
    if (tid < NPL) {
        float s = wt[15][tid];
#pragma unroll
        for (int j = 0; j < 15; j++) s += 2.0f * wt[j][tid];
        const float inv = 1.0f / s;
#pragma unroll
        for (int j = 0; j < 16; j++) wt[j][tid] *= inv;
    }
    __syncthreads();

    // ---- symmetric half-kernels into registers (conflict-free LDS) ----
    float wA[16], wB[16], wC[16], wD[16];
#pragma unroll
    for (int j = 0; j < 16; j++) {
        wA[j] = wt[j][p0]; wB[j] = wt[j][p1];
        wC[j] = wt[j][p2]; wD[j] = wt[j][p3];
    }

    float* ob = out + (size_t)b * CCH * HH * WW;

    // ---- channel-outer loop; channels 1,2 land under channel-0 compute ----
    // Window value u (rel col 4tx+u): pixel P's tap tau reads u = tau + 1 + P.
#pragma unroll 1
    for (int c = 0; c < CCH; c++) {
        if (c == 1) { cp_wait<1>(); __syncthreads(); }
        if (c == 2) { cp_wait<0>(); __syncthreads(); }

        const float* tc = &tile[c][0][0];
        float accA = 0.f, accB = 0.f, accC = 0.f, accD = 0.f;

#pragma unroll 2
        for (int s = 0; s < 16; s++) {
            const float hs = (s == 15) ? 0.5f : 1.0f;   // self-pair at center
            const float gA = wt[s][p0] * hs;
            const float gB = wt[s][p1] * hs;
            const float gC = wt[s][p2] * hs;
            const float gD = wt[s][p3] * hs;

            const float* ra = tc + (ty + s) * SWP + 4 * tx;
            const float* rb = tc + (ty + 30 - s) * SWP + 4 * tx;

            float Fp[4], Fc[4];
            {
                float4 qa = *(const float4*)ra;
                float4 qb = *(const float4*)rb;
                Fp[0] = qa.x + qb.x; Fp[1] = qa.y + qb.y;
                Fp[2] = qa.z + qb.z; Fp[3] = qa.w + qb.w;
            }
            float a = 0.f, bb = 0.f, cc2 = 0.f, d = 0.f;
#pragma unroll
            for (int m = 1; m <= 8; m++) {
                float4 qa = *(const float4*)(ra + 4 * m);
                float4 qb = *(const float4*)(rb + 4 * m);
                Fc[0] = qa.x + qb.x; Fc[1] = qa.y + qb.y;
                Fc[2] = qa.z + qb.z; Fc[3] = qa.w + qb.w;
#pragma unroll
                for (int t = 0; t < 4; t++) {
                    const int tau = 4 * (m - 1) + t;
                    if (tau <= 30) {
                        const int sj = SYMI(tau);
                        a   += wA[sj] * ((t < 3) ? Fp[t + 1] : Fc[0]);
                        bb  += wB[sj] * ((t < 2) ? Fp[t + 2] : Fc[t - 2]);
                        cc2 += wC[sj] * ((t < 1) ? Fp[t + 3] : Fc[t - 1]);
                        d   += wD[sj] * Fc[t];
                    }
                }
                Fp[0] = Fc[0]; Fp[1] = Fc[1]; Fp[2] = Fc[2]; Fp[3] = Fc[3];
            }
            accA += gA * a;
            accB += gB * bb;
            accC += gC * cc2;
            accD += gD * d;
        }
        *(float4*)(ob + ((size_t)c * HH + y) * WW + xA) =
            make_float4(accA, accB, accC, accD);
    }
}

// ---------------------------------------------------------------------------
extern "C" void kernel_launch(void* const* d_in, const int* in_sizes, int n_in,
                              void* d_out, int out_size) {
    const float* sharp = (const float*)d_in[0];
    const float* coc   = (const float*)d_in[1];
    if (n_in >= 2 && in_sizes[0] == BQ * HH * WW && in_sizes[1] == BQ * CCH * HH * WW) {
        sharp = (const float*)d_in[1];   // defensive input-order swap
        coc   = (const float*)d_in[0];
    }
    float* out = (float*)d_out;

    dim3 grid(WW / TW, HH / TH, BQ);    // (16, 32, 4)
    dim3 block(8, 16);
    defocus_kernel<<<grid, block>>>(sharp, coc, out);
}

// round 12
// speedup vs baseline: 1.5592x; 1.0899x over previous
#include <cuda_runtime.h>
#include <math.h>
#include <stdint.h>

#define BQ   4
#define CCH  3
#define HH   512
#define WW   512
#define NPL  32
#define TW   32            // tile width  (8 threads x 4 px)
#define TH   16            // tile height
#define HALO_L 16          // left halo (16B-aligned quads)
#define SWP  64            // 16 quads per row
#define SH   (TH + 30)     // 46 halo rows
#define QPR  16
#define NQ   (SH * QPR)    // 736 quads per channel

#define NTILE_X 16
#define NTILE_Y 32
#define NTILES  (NTILE_X * NTILE_Y * BQ)   // 2048
#define NCTA    740                        // 5 CTAs/SM x 148 SMs

#define SYMI(d) ((d) < 16 ? (d) : 30 - (d))

__device__ constexpr float midp(int i) {
    return ((float)(i * (50.0 / 31.0)) + (float)((i + 1) * (50.0 / 31.0))) * 0.5f;
}

__device__ __forceinline__ void cp_async16(uint32_t daddr, const void* src, int srcsize) {
    asm volatile("cp.async.cg.shared.global [%0], [%1], 16, %2;"
                 :: "r"(daddr), "l"(src), "r"(srcsize) : "memory");
}
__device__ __forceinline__ void cp_commit() {
    asm volatile("cp.async.commit_group;" ::: "memory");
}
template <int N>
__device__ __forceinline__ void cp_wait() {
    asm volatile("cp.async.wait_group %0;" :: "n"(N) : "memory");
}

__global__ void __launch_bounds__(128, 5)
defocus_kernel(const float* __restrict__ sharp,
               const float* __restrict__ coc,
               float* __restrict__ out) {
    __shared__ float tile[CCH][SH][SWP];   // 35328 B (rotating channel bufs)
    __shared__ float wt[16][32];           // transposed folded table (bank=plane)

    const int tx  = threadIdx.x;           // 0..7
    const int ty  = threadIdx.y;           // 0..15
    const int tid = ty * 8 + tx;

    // ---- weight table phase 1: unnormalized entries ----
    const double step = 50.0 / 31.0;
#pragma unroll
    for (int idx = tid; idx < NPL * 16; idx += 128) {
        const int i = idx & 31;            // plane
        const int j = idx >> 5;            // folded tap (15 = center)
        const float cocf = (float)(i * step);
        float e;
        if (cocf < 0.5f) {
            e = (j == 15) ? 1.0f : 0.0f;
        } else {
            double cd = (double)cocf;
            int k = (int)(2.0 * cd + 1.0);
            if (!(k & 1)) k++;
            if (k > 31) k = 31;
            const int half = k >> 1;
            const int d = 15 - j;
            if (d > half) {
                e = 0.0f;
            } else {
                double sg = cd / 2.355;
                float inv2 = (float)(1.0 / (2.0 * sg * sg));
                e = expf(-(float)(d * d) * inv2);
            }
        }
        wt[j][i] = e;
    }

    // ---- tile-channel async load helper (macro to keep regs flat) ----
#define ISSUE_CH(t_, c_)                                                        \
    do {                                                                        \
        int bx_ = (t_) & (NTILE_X - 1);                                         \
        int by_ = ((t_) >> 4) & (NTILE_Y - 1);                                  \
        int bb_ = (t_) >> 9;                                                    \
        int xo_ = bx_ * TW, yo_ = by_ * TH;                                     \
        const float* sc_ = sharp + ((size_t)(bb_ * CCH + (c_))) * HH * WW;      \
        _Pragma("unroll")                                                       \
        for (int u_ = 0; u_ < 6; u_++) {                                        \
            int q_ = u_ * 128 + tid;                                            \
            if (q_ < NQ) {                                                      \
                int r_ = q_ >> 4;                                               \
                int qq_ = q_ & 15;                                              \
                int gx_ = xo_ - HALO_L + 4 * qq_;                               \
                int gy_ = yo_ - 15 + r_;                                        \
                bool ok_ = ((unsigned)gx_ <= (unsigned)(WW - 4)) &&             \
                           ((unsigned)gy_ <  (unsigned)HH);                     \
                const float* s_ = sc_ + (ok_ ? (gy_ * WW + gx_) : 0);           \
                uint32_t d_ = (uint32_t)__cvta_generic_to_shared(               \
                                  &tile[c_][r_][4 * qq_]);                      \
                cp_async16(d_, s_, ok_ ? 16 : 0);                               \
            }                                                                   \
        }                                                                       \
    } while (0)

    // ---- prologue: first tile's 3 channel groups in flight ----
    const int t0 = blockIdx.x;
    ISSUE_CH(t0, 0); cp_commit();
    ISSUE_CH(t0, 1); cp_commit();
    ISSUE_CH(t0, 2); cp_commit();

    __syncthreads();                       // phase-1 wt writes visible

    // ---- weight table phase 2: normalize plane columns (bank = tid) ----
    if (tid < NPL) {
        float s = wt[15][tid];
#pragma unroll
        for (int j = 0; j < 15; j++) s += 2.0f * wt[j][tid];
        const float inv = 1.0f / s;
#pragma unroll
        for (int j = 0; j < 16; j++) wt[j][tid] *= inv;
    }
    __syncthreads();

    // ---- persistent tile loop ----
    for (int t = t0; t < NTILES; t += NCTA) {
        const int bx = t & (NTILE_X - 1);
        const int by = (t >> 4) & (NTILE_Y - 1);
        const int b  = t >> 9;
        const int x0 = bx * TW;
        const int y0 = by * TH;
        const int xA = x0 + 4 * tx;
        const int y  = y0 + ty;

        // plane bucketing (immediate midpoints)
        const float4 c4 = *(const float4*)(coc + ((size_t)b * HH + y) * WW + xA);
        int p0 = 0, p1 = 0, p2 = 0, p3 = 0;
#pragma unroll
        for (int i = 0; i < 31; i++) {
            const float m = midp(i);
            p0 += c4.x > m; p1 += c4.y > m; p2 += c4.z > m; p3 += c4.w > m;
        }

        // symmetric half-kernels into regs (conflict-free LDS: bank = plane)
        float wA[16], wB[16], wC[16], wD[16];
#pragma unroll
        for (int j = 0; j < 16; j++) {
            wA[j] = wt[j][p0]; wB[j] = wt[j][p1];
            wC[j] = wt[j][p2]; wD[j] = wt[j][p3];
        }

        float* ob = out + (size_t)b * CCH * HH * WW;
        const int tn = t + NCTA;           // next tile for this CTA

#pragma unroll 1
        for (int c = 0; c < CCH; c++) {
            cp_wait<2>();                  // exactly the (t,c) group retires
            __syncthreads();               // all threads' copies visible

            const float* tc = &tile[c][0][0];
            float accA = 0.f, accB = 0.f, accC = 0.f, accD = 0.f;

#pragma unroll 2
            for (int s = 0; s < 16; s++) {
                const float hs = (s == 15) ? 0.5f : 1.0f;
                const float gA = wt[s][p0] * hs;
                const float gB = wt[s][p1] * hs;
                const float gC = wt[s][p2] * hs;
                const float gD = wt[s][p3] * hs;

                const float* ra = tc + (ty + s) * SWP + 4 * tx;
                const float* rb = tc + (ty + 30 - s) * SWP + 4 * tx;

                float Fp[4], Fc[4];
                {
                    float4 qa = *(const float4*)ra;
                    float4 qb = *(const float4*)rb;
                    Fp[0] = qa.x + qb.x; Fp[1] = qa.y + qb.y;
                    Fp[2] = qa.z + qb.z; Fp[3] = qa.w + qb.w;
                }
                float a = 0.f, bb2 = 0.f, cc2 = 0.f, d = 0.f;
#pragma unroll
                for (int m = 1; m <= 8; m++) {
                    float4 qa = *(const float4*)(ra + 4 * m);
                    float4 qb = *(const float4*)(rb + 4 * m);
                    Fc[0] = qa.x + qb.x; Fc[1] = qa.y + qb.y;
                    Fc[2] = qa.z + qb.z; Fc[3] = qa.w + qb.w;
#pragma unroll
                    for (int tt = 0; tt < 4; tt++) {
                        const int tau = 4 * (m - 1) + tt;
                        if (tau <= 30) {
                            const int sj = SYMI(tau);
                            a   += wA[sj] * ((tt < 3) ? Fp[tt + 1] : Fc[0]);
                            bb2 += wB[sj] * ((tt < 2) ? Fp[tt + 2] : Fc[tt - 2]);
                            cc2 += wC[sj] * ((tt < 1) ? Fp[tt + 3] : Fc[tt - 1]);
                            d   += wD[sj] * Fc[tt];
                        }
                    }
                    Fp[0] = Fc[0]; Fp[1] = Fc[1]; Fp[2] = Fc[2]; Fp[3] = Fc[3];
                }
                accA += gA * a;
                accB += gB * bb2;
                accC += gC * cc2;
                accD += gD * d;
            }
            *(float4*)(ob + ((size_t)c * HH + y) * WW + xA) =
                make_float4(accA, accB, accC, accD);

            __syncthreads();               // buffer c free for refill
            if (tn < NTILES) ISSUE_CH(tn, c);
            cp_commit();                   // empty group if no issue: keeps
        }                                  // the wait<2> accounting uniform
    }
#undef ISSUE_CH
}

// ---------------------------------------------------------------------------
extern "C" void kernel_launch(void* const* d_in, const int* in_sizes, int n_in,
                              void* d_out, int out_size) {
    const float* sharp = (const float*)d_in[0];
    const float* coc   = (const float*)d_in[1];
    if (n_in >= 2 && in_sizes[0] == BQ * HH * WW && in_sizes[1] == BQ * CCH * HH * WW) {
        sharp = (const float*)d_in[1];   // defensive input-order swap
        coc   = (const float*)d_in[0];
    }
    float* out = (float*)d_out;

    dim3 grid(NCTA, 1, 1);               // persistent: 5 CTAs/SM x 148 SMs
    dim3 block(8, 16);
    defocus_kernel<<<grid, block>>>(sharp, coc, out);
}

// round 13
// speedup vs baseline: 1.6260x; 1.0429x over previous
#include <cuda_runtime.h>
#include <math.h>
#include <stdint.h>

#define BQ   4
#define CCH  3
#define HH   512
#define WW   512
#define NPL  32
#define TW   32            // tile width  (8 threads x 4 px)
#define TH   16            // tile height
#define HALO_L 16          // left halo (16B-aligned quads)
#define SWP  64            // 16 quads per row
#define SH   (TH + 30)     // 46 halo rows
#define QPR  16
#define NQ   (SH * QPR)    // 736 quads per channel

#define NTILE_X 16
#define NTILE_Y 32
#define NTILES  (NTILE_X * NTILE_Y * BQ)   // 2048
#define NCTA    740                        // 5 CTAs/SM x 148 SMs

#define SYMI(d) ((d) < 16 ? (d) : 30 - (d))

__device__ constexpr float midp(int i) {
    return ((float)(i * (50.0 / 31.0)) + (float)((i + 1) * (50.0 / 31.0))) * 0.5f;
}

__device__ __forceinline__ void cp_async16(uint32_t daddr, const void* src, int srcsize) {
    asm volatile("cp.async.cg.shared.global [%0], [%1], 16, %2;"
                 :: "r"(daddr), "l"(src), "r"(srcsize) : "memory");
}
__device__ __forceinline__ void cp_commit() {
    asm volatile("cp.async.commit_group;" ::: "memory");
}
template <int N>
__device__ __forceinline__ void cp_wait() {
    asm volatile("cp.async.wait_group %0;" :: "n"(N) : "memory");
}

__global__ void __launch_bounds__(128, 5)
defocus_kernel(const float* __restrict__ sharp,
               const float* __restrict__ coc,
               float* __restrict__ out) {
    __shared__ float tile[CCH][SH][SWP];   // 35328 B (rotating channel bufs)
    __shared__ float wt[16][32];           // transposed folded table (bank=plane)
    __shared__ float fscr[4][4][SWP];      // per-warp folded rows: 4096 B

    const int tx  = threadIdx.x;           // 0..7
    const int ty  = threadIdx.y;           // 0..15
    const int tid = ty * 8 + tx;
    const int wk  = tid >> 5;              // warp 0..3  (covers ty = 4wk..4wk+3)
    const int l   = tid & 31;              // lane
    const int jj1 = l >> 4;                // fold rows handled: jj1 and jj1+2
    const int chk = l & 15;                // 4-float chunk within row

    // ---- weight table phase 1: unnormalized entries ----
    const double step = 50.0 / 31.0;
#pragma unroll
    for (int idx = tid; idx < NPL * 16; idx += 128) {
        const int i = idx & 31;            // plane
        const int j = idx >> 5;            // folded tap (15 = center)
        const float cocf = (float)(i * step);
        float e;
        if (cocf < 0.5f) {
            e = (j == 15) ? 1.0f : 0.0f;
        } else {
            double cd = (double)cocf;
            int k = (int)(2.0 * cd + 1.0);
            if (!(k & 1)) k++;
            if (k > 31) k = 31;
            const int half = k >> 1;
            const int d = 15 - j;
            if (d > half) {
                e = 0.0f;
            } else {
                double sg = cd / 2.355;
                float inv2 = (float)(1.0 / (2.0 * sg * sg));
                e = expf(-(float)(d * d) * inv2);
            }
        }
        wt[j][i] = e;
    }

#define ISSUE_CH(t_, c_)                                                        \
    do {                                                                        \
        int bx_ = (t_) & (NTILE_X - 1);                                         \
        int by_ = ((t_) >> 4) & (NTILE_Y - 1);                                  \
        int bb_ = (t_) >> 9;                                                    \
        int xo_ = bx_ * TW, yo_ = by_ * TH;                                     \
        const float* sc_ = sharp + ((size_t)(bb_ * CCH + (c_))) * HH * WW;      \
        _Pragma("unroll")                                                       \
        for (int u_ = 0; u_ < 6; u_++) {                                        \
            int q_ = u_ * 128 + tid;                                            \
            if (q_ < NQ) {                                                      \
                int r_ = q_ >> 4;                                               \
                int qq_ = q_ & 15;                                              \
                int gx_ = xo_ - HALO_L + 4 * qq_;                               \
                int gy_ = yo_ - 15 + r_;                                        \
                bool ok_ = ((unsigned)gx_ <= (unsigned)(WW - 4)) &&             \
                           ((unsigned)gy_ <  (unsigned)HH);                     \
                const float* s_ = sc_ + (ok_ ? (gy_ * WW + gx_) : 0);           \
                uint32_t d_ = (uint32_t)__cvta_generic_to_shared(               \
                                  &tile[c_][r_][4 * qq_]);                      \
                cp_async16(d_, s_, ok_ ? 16 : 0);                               \
            }                                                                   \
        }                                                                       \
    } while (0)

    // ---- prologue: first tile's 3 channel groups in flight ----
    const int t0 = blockIdx.x;
    ISSUE_CH(t0, 0); cp_commit();
    ISSUE_CH(t0, 1); cp_commit();
    ISSUE_CH(t0, 2); cp_commit();

    __syncthreads();                       // phase-1 wt writes visible

    // ---- weight table phase 2: normalize plane columns (bank = tid) ----
    if (tid < NPL) {
        float s = wt[15][tid];
#pragma unroll
        for (int j = 0; j < 15; j++) s += 2.0f * wt[j][tid];
        const float inv = 1.0f / s;
#pragma unroll
        for (int j = 0; j < 16; j++) wt[j][tid] *= inv;
    }
    __syncthreads();

    // ---- persistent tile loop ----
    for (int t = t0; t < NTILES; t += NCTA) {
        const int bx = t & (NTILE_X - 1);
        const int by = (t >> 4) & (NTILE_Y - 1);
        const int b  = t >> 9;
        const int x0 = bx * TW;
        const int y0 = by * TH;
        const int xA = x0 + 4 * tx;
        const int y  = y0 + ty;

        // plane bucketing (immediate midpoints)
        const float4 c4 = *(const float4*)(coc + ((size_t)b * HH + y) * WW + xA);
        int p0 = 0, p1 = 0, p2 = 0, p3 = 0;
#pragma unroll
        for (int i = 0; i < 31; i++) {
            const float m = midp(i);
            p0 += c4.x > m; p1 += c4.y > m; p2 += c4.z > m; p3 += c4.w > m;
        }

        // symmetric half-kernels into regs (conflict-free LDS: bank = plane)
        float wA[16], wB[16], wC[16], wD[16];
#pragma unroll
        for (int j = 0; j < 16; j++) {
            wA[j] = wt[j][p0]; wB[j] = wt[j][p1];
            wC[j] = wt[j][p2]; wD[j] = wt[j][p3];
        }

        float* ob = out + (size_t)b * CCH * HH * WW;
        const int tn = t + NCTA;           // next tile for this CTA

#pragma unroll 1
        for (int c = 0; c < CCH; c++) {
            cp_wait<2>();                  // exactly the (t,c) group retires
            __syncthreads();               // all threads' copies visible

            const float* tc = &tile[c][0][0];
            const float* fr = &fscr[wk][ty & 3][4 * tx];  // this thread's window
            float accA = 0.f, accB = 0.f, accC = 0.f, accD = 0.f;

#pragma unroll 1
            for (int s = 0; s < 16; s++) {
                const float hs = (s == 15) ? 0.5f : 1.0f;
                const float gA = wt[s][p0] * hs;
                const float gB = wt[s][p1] * hs;
                const float gC = wt[s][p2] * hs;
                const float gD = wt[s][p3] * hs;

                // -- warp-cooperative fold of this warp's 4 row-pairs --
                __syncwarp();              // WAR: prior reads of fscr done
                {
                    const float* basep = tc + 4 * chk;
#pragma unroll
                    for (int jj = jj1; jj < 4; jj += 2) {
                        const int rA = 4 * wk + jj + s;
                        const int rB = 4 * wk + jj + 30 - s;
                        float4 qa = *(const float4*)(basep + rA * SWP);
                        float4 qb = *(const float4*)(basep + rB * SWP);
                        float4 f;
                        f.x = qa.x + qb.x; f.y = qa.y + qb.y;
                        f.z = qa.z + qb.z; f.w = qa.w + qb.w;
                        *(float4*)&fscr[wk][jj][4 * chk] = f;
                    }
                }
                __syncwarp();              // RAW: folds visible to warp

                // -- H-pass on the folded row (streaming window) --
                float4 Fp = *(const float4*)fr;
                float a = 0.f, bb2 = 0.f, cc2 = 0.f, d = 0.f;
#pragma unroll
                for (int m = 1; m <= 8; m++) {
                    float4 Fc = *(const float4*)(fr + 4 * m);
                    const float fp[4] = {Fp.x, Fp.y, Fp.z, Fp.w};
                    const float fc[4] = {Fc.x, Fc.y, Fc.z, Fc.w};
#pragma unroll
                    for (int tt = 0; tt < 4; tt++) {
                        const int tau = 4 * (m - 1) + tt;
                        if (tau <= 30) {
                            const int sj = SYMI(tau);
                            a   += wA[sj] * ((tt < 3) ? fp[tt + 1] : fc[0]);
                            bb2 += wB[sj] * ((tt < 2) ? fp[tt + 2] : fc[tt - 2]);
                            cc2 += wC[sj] * ((tt < 1) ? fp[tt + 3] : fc[tt - 1]);
                            d   += wD[sj] * fc[tt];
                        }
                    }
                    Fp = Fc;
                }
                accA += gA * a;
                accB += gB * bb2;
                accC += gC * cc2;
                accD += gD * d;
            }
            *(float4*)(ob + ((size_t)c * HH + y) * WW + xA) =
                make_float4(accA, accB, accC, accD);

            __syncthreads();               // buffer c free for refill
            if (tn < NTILES) ISSUE_CH(tn, c);
            cp_commit();                   // empty group keeps wait<2> uniform
        }
    }
#undef ISSUE_CH
}

// ---------------------------------------------------------------------------
extern "C" void kernel_launch(void* const* d_in, const int* in_sizes, int n_in,
                              void* d_out, int out_size) {
    const float* sharp = (const float*)d_in[0];
    const float* coc   = (const float*)d_in[1];
    if (n_in >= 2 && in_sizes[0] == BQ * HH * WW && in_sizes[1] == BQ * CCH * HH * WW) {
        sharp = (const float*)d_in[1];   // defensive input-order swap
        coc   = (const float*)d_in[0];
    }
    float* out = (float*)d_out;

    dim3 grid(NCTA, 1, 1);               // persistent: 5 CTAs/SM x 148 SMs
    dim3 block(8, 16);
    defocus_kernel<<<grid, block>>>(sharp, coc, out);
}